// round 7
// baseline (speedup 1.0000x reference)
#include <cuda_runtime.h>
#include <cuda_bf16.h>

#define BATCH   64
#define CDIM    64
#define WDIM    16384
#define SPLITS  2
#define KSPLIT  (WDIM / SPLITS)     // 8192
#define KT      128
#define NCHUNK  (KSPLIT / KT)       // 64
#define SMS     136                 // smem row stride in bf16 elems (272 B = 17*16B)

// Scratch (static device arrays; no allocation)
__device__ float g_part[BATCH * SPLITS * CDIM * CDIM];  // 2 MB
__device__ float g_mat [BATCH * CDIM * CDIM];           // 1 MB
__device__ float d_mat [BATCH * BATCH];

__device__ __forceinline__ unsigned smem_u32(const void* p) {
    return (unsigned)__cvta_generic_to_shared(p);
}

__device__ __forceinline__ void ldsm_x4(unsigned addr, unsigned &r0, unsigned &r1,
                                        unsigned &r2, unsigned &r3) {
    asm volatile("ldmatrix.sync.aligned.m8n8.x4.shared.b16 {%0,%1,%2,%3}, [%4];\n"
                 : "=r"(r0), "=r"(r1), "=r"(r2), "=r"(r3) : "r"(addr));
}

__device__ __forceinline__ void mma_bf16(float* c, unsigned a0, unsigned a1,
                                         unsigned a2, unsigned a3,
                                         unsigned b0, unsigned b1) {
    asm volatile(
        "mma.sync.aligned.m16n8k16.row.col.f32.bf16.bf16.f32 "
        "{%0,%1,%2,%3}, {%4,%5,%6,%7}, {%8,%9}, {%0,%1,%2,%3};\n"
        : "+f"(c[0]), "+f"(c[1]), "+f"(c[2]), "+f"(c[3])
        : "r"(a0), "r"(a1), "r"(a2), "r"(a3), "r"(b0), "r"(b1));
}

// ---------------------------------------------------------------------------
// Kernel 1: partial Gram matrices. grid = 128 (batch x split), 256 threads.
// Each CTA: G_part[b][s] = X[b][:, sK:(s+1)K] * X^T  (64x64, fp32 acc, bf16 MMA)
// ---------------------------------------------------------------------------
__global__ __launch_bounds__(256, 1) void gram_kernel(const float* __restrict__ inp) {
    __shared__ __align__(16) __nv_bfloat16 tile[CDIM * SMS];

    const int bid  = blockIdx.x;
    const int b    = bid >> 1;
    const int s    = bid & 1;
    const int tid  = threadIdx.x;
    const int lane = tid & 31;
    const int warp = tid >> 5;

    // ---- loader mapping: threads 0..127, 2 threads per row, 16 float4 each
    const int lrow  = tid >> 1;
    const int lhalf = tid & 1;
    const float4* srow = reinterpret_cast<const float4*>(inp)
                       + (long)(b * CDIM + lrow) * (WDIM / 4)
                       + s * (KSPLIT / 4) + lhalf;
    char* tb = reinterpret_cast<char*>(tile);
    const int sts_base = lrow * (SMS * 2) + lhalf * 8;   // bytes

    float4 pre[16];
    const bool loader = (tid < 128);
    if (loader) {
#pragma unroll
        for (int j = 0; j < 16; ++j) pre[j] = srow[2 * j];
    }

    // ---- MMA mapping: 8 warps, warp tile 16x32
    const int wm = (warp & 3) * 16;
    const int wn = (warp >> 2) * 32;
    const unsigned smb = smem_u32(tile);
    const unsigned aAddr  = smb + (unsigned)((wm + (lane & 7) + 8 * ((lane >> 3) & 1)) * (SMS * 2)
                                             + (lane >> 4) * 16);
    const unsigned bAddr0 = smb + (unsigned)((wn + (lane & 7) + 8 * (lane >> 4)) * (SMS * 2)
                                             + ((lane >> 3) & 1) * 16);
    const unsigned bAddr1 = bAddr0 + 16u * (SMS * 2);

    float acc[4][4];
#pragma unroll
    for (int n = 0; n < 4; ++n)
#pragma unroll
        for (int r = 0; r < 4; ++r) acc[n][r] = 0.0f;

    for (int c = 0; c < NCHUNK; ++c) {
        if (loader) {
#pragma unroll
            for (int j = 0; j < 16; ++j) {
                __nv_bfloat162 p0 = __floats2bfloat162_rn(pre[j].x, pre[j].y);
                __nv_bfloat162 p1 = __floats2bfloat162_rn(pre[j].z, pre[j].w);
                uint2 u;
                u.x = *reinterpret_cast<unsigned*>(&p0);
                u.y = *reinterpret_cast<unsigned*>(&p1);
                *reinterpret_cast<uint2*>(tb + sts_base + 16 * j) = u;
            }
        }
        __syncthreads();
        if (loader && (c + 1 < NCHUNK)) {
            const float4* nsrc = srow + (long)(c + 1) * (KT / 4);
#pragma unroll
            for (int j = 0; j < 16; ++j) pre[j] = nsrc[2 * j];
        }
#pragma unroll
        for (int kk = 0; kk < 8; ++kk) {
            const unsigned koff = kk * 32;   // 16 bf16 = 32 bytes
            unsigned a0, a1, a2, a3, b00, b01, b10, b11, b20, b21, b30, b31;
            ldsm_x4(aAddr + koff, a0, a1, a2, a3);
            ldsm_x4(bAddr0 + koff, b00, b01, b10, b11);
            ldsm_x4(bAddr1 + koff, b20, b21, b30, b31);
            mma_bf16(acc[0], a0, a1, a2, a3, b00, b01);
            mma_bf16(acc[1], a0, a1, a2, a3, b10, b11);
            mma_bf16(acc[2], a0, a1, a2, a3, b20, b21);
            mma_bf16(acc[3], a0, a1, a2, a3, b30, b31);
        }
        __syncthreads();
    }

    // ---- epilogue: write partial Gram (fp32)
    float* gp = g_part + (long)(b * SPLITS + s) * CDIM * CDIM;
    const int row0 = wm + (lane >> 2);
#pragma unroll
    for (int ni = 0; ni < 4; ++ni) {
        const int col = wn + 8 * ni + 2 * (lane & 3);
        *reinterpret_cast<float2*>(gp + row0 * CDIM + col)       = make_float2(acc[ni][0], acc[ni][1]);
        *reinterpret_cast<float2*>(gp + (row0 + 8) * CDIM + col) = make_float2(acc[ni][2], acc[ni][3]);
    }
}

// ---------------------------------------------------------------------------
// Kernel 2: reduce split partials and normalize by 1/(C*W)
// ---------------------------------------------------------------------------
__global__ void reduce_kernel() {
    const int b = blockIdx.x;
    const float inv = 1.0f / ((float)CDIM * (float)WDIM);
    const float* p0 = g_part + (long)(b * 2) * 4096;
    const float* p1 = p0 + 4096;
    float* g = g_mat + (long)b * 4096;
    for (int i = threadIdx.x; i < 4096; i += blockDim.x)
        g[i] = (p0[i] + p1[i]) * inv;
}

// ---------------------------------------------------------------------------
// Kernel 3: pairwise distances D[i][j] = mean((G_i - G_j)^2)
// grid = 64 (i), 256 threads; warp w handles j = w, w+8, ...
// ---------------------------------------------------------------------------
__global__ void dist_kernel() {
    __shared__ float gi[4096];
    const int i = blockIdx.x;
    for (int t = threadIdx.x; t < 4096; t += 256) gi[t] = g_mat[(long)i * 4096 + t];
    __syncthreads();
    const int warp = threadIdx.x >> 5;
    const int lane = threadIdx.x & 31;
    for (int j = warp; j < BATCH; j += 8) {
        const float* __restrict__ gj = g_mat + (long)j * 4096;
        float sum = 0.0f;
#pragma unroll 4
        for (int c = lane; c < 4096; c += 32) {
            float d = gi[c] - gj[c];
            sum = fmaf(d, d, sum);
        }
#pragma unroll
        for (int o = 16; o > 0; o >>= 1) sum += __shfl_xor_sync(0xffffffffu, sum, o);
        if (lane == 0) d_mat[i * BATCH + j] = sum * (1.0f / 4096.0f);
    }
}

// ---------------------------------------------------------------------------
// Kernel 4: final loss. Single CTA.
// Target dtype is detected at runtime: JAX with x64 disabled demotes the
// reference's int64 targets to int32. We read the first 256 bytes as int32;
// if every odd word is zero the buffer is little-endian int64 (prob. of
// false positive for genuine int32 targets in [0,8): (1/8)^32 ~ 8e-29).
// The int64 read path only touches bytes that exist in that case.
// ---------------------------------------------------------------------------
__global__ void loss_kernel(const void* __restrict__ tgt_raw, float* __restrict__ out) {
    __shared__ float D[4096];
    __shared__ float Sn[64];
    __shared__ int   Tg[64];
    __shared__ float red[256];
    __shared__ int   redc[256];
    __shared__ int   is64;
    const int tid = threadIdx.x;

    const int* t32 = (const int*)tgt_raw;
    if (tid == 0) {
        int f = 0;
#pragma unroll
        for (int k = 1; k < 64; k += 2) f |= t32[k];
        is64 = (f == 0) ? 1 : 0;
    }
    for (int t = tid; t < 4096; t += 256) D[t] = d_mat[t];
    __syncthreads();
    if (tid < 64) {
        if (is64) Tg[tid] = (int)((const long long*)tgt_raw)[tid];
        else      Tg[tid] = t32[tid];
    }
    __syncthreads();

    if (tid < 64) {
        const int ti = Tg[tid];
        float ssum = 0.0f;
#pragma unroll 4
        for (int k = 0; k < 64; ++k)
            if (Tg[k] != ti) ssum += expf(1.0f - D[tid * 64 + k]);
        Sn[tid] = ssum;
    }
    __syncthreads();

    float acc = 0.0f;
    int cnt = 0;
    for (int p = tid; p < 4096; p += 256) {
        const int i = p >> 6, j = p & 63;
        if (j > i && Tg[i] == Tg[j]) {
            float Jv = logf(Sn[i] + Sn[j]) + D[p];
            Jv = fmaxf(Jv, 0.0f);
            acc += Jv * Jv;
            cnt++;
        }
    }
    red[tid] = acc;
    redc[tid] = cnt;
    __syncthreads();
    for (int o = 128; o > 0; o >>= 1) {
        if (tid < o) { red[tid] += red[tid + o]; redc[tid] += redc[tid + o]; }
        __syncthreads();
    }
    if (tid == 0) out[0] = red[0] / (2.0f * (float)redc[0]);
}

// ---------------------------------------------------------------------------
extern "C" void kernel_launch(void* const* d_in, const int* in_sizes, int n_in,
                              void* d_out, int out_size) {
    const float* inp = (const float*)d_in[0];
    const void*  tgt = (const void*)d_in[1];
    float*       out = (float*)d_out;

    gram_kernel<<<BATCH * SPLITS, 256>>>(inp);
    reduce_kernel<<<BATCH, 256>>>();
    dist_kernel<<<BATCH, 256>>>();
    loss_kernel<<<1, 256>>>(tgt, out);
}

// round 11
// speedup vs baseline: 2.4748x; 2.4748x over previous
#include <cuda_runtime.h>
#include <cuda_bf16.h>
#include <cstdint>

#define BATCH   64
#define CDIM    64
#define WDIM    16384
#define SPLITS  4
#define KSP     (WDIM / SPLITS)      // 4096 fp32 cols per CTA
#define KTF     128                  // fp32 cols per chunk
#define NCH     (KSP / KTF)          // 32 chunks

// Scratch (static device arrays; no allocation)
__device__ float g_part[BATCH * SPLITS * 4096];   // 4 MB
__device__ float g_mat [BATCH * 4096];            // 1 MB
__device__ float d_mat [BATCH * BATCH];
__device__ float g_Sn  [BATCH];
__device__ int   g_cnt1, g_cnt2;

__device__ __forceinline__ unsigned cvta_s(const void* p) {
    return (unsigned)__cvta_generic_to_shared(p);
}

__device__ __forceinline__ void ldsm_x4(unsigned addr, unsigned &r0, unsigned &r1,
                                        unsigned &r2, unsigned &r3) {
    asm volatile("ldmatrix.sync.aligned.m8n8.x4.shared.b16 {%0,%1,%2,%3}, [%4];\n"
                 : "=r"(r0), "=r"(r1), "=r"(r2), "=r"(r3) : "r"(addr));
}

__device__ __forceinline__ void mma_bf16(float* c, unsigned a0, unsigned a1,
                                         unsigned a2, unsigned a3,
                                         unsigned b0, unsigned b1) {
    asm volatile(
        "mma.sync.aligned.m16n8k16.row.col.f32.bf16.bf16.f32 "
        "{%0,%1,%2,%3}, {%4,%5,%6,%7}, {%8,%9}, {%0,%1,%2,%3};\n"
        : "+f"(c[0]), "+f"(c[1]), "+f"(c[2]), "+f"(c[3])
        : "r"(a0), "r"(a1), "r"(a2), "r"(a3), "r"(b0), "r"(b1));
}

// ---------------------------------------------------------------------------
// Kernel 1: partial Grams. grid = 256 (batch x split), 256 threads, occ 2.
// CTA (b, s): G_part[b][s] = X[b][:, sK:(s+1)K] * X^T  (64x64 fp32 acc).
// smem layout: 2 stages x 64 rows x 256B; 16B unit u stored at u^(row&7).
// 8 warps: 2x2 spatial tiles (32x32) x 2 k-groups (4 of 8 k16-steps each).
// ---------------------------------------------------------------------------
__global__ __launch_bounds__(256, 2) void gram_kernel(const float* __restrict__ inp) {
    __shared__ __align__(1024) __nv_bfloat16 tile[2][64 * 128];   // 2 x 16 KB

    const int tid = threadIdx.x, wid = tid >> 5, lane = tid & 31;
    const int bid = blockIdx.x, b = bid >> 2, s = bid & 3;

    if (bid == 0 && tid == 0) { g_cnt1 = 0; g_cnt2 = 0; }   // grid-barrier reset

    // ---- loader mapping: row = tid>>2 (0..63), q = tid&3; 8 float4/chunk
    const int row = tid >> 2, q = tid & 3, rx = row & 7;
    const float4* src = reinterpret_cast<const float4*>(inp)
                      + (long)(b * CDIM + row) * (WDIM / 4) + s * (KSP / 4) + 2 * q;
    const unsigned stbase = cvta_s(&tile[0][0]);
    unsigned sts_off[4];
#pragma unroll
    for (int j = 0; j < 4; ++j)
        sts_off[j] = (unsigned)(row * 256 + (((4 * j + q) ^ rx) << 4));

    // ---- MMA mapping
    const int tlid = wid & 3;                 // spatial tile
    const int tm = (tlid & 1) * 32, tn = (tlid >> 1) * 32;
    const int kg = wid >> 2;                  // k-group (ksteps kg*4 .. kg*4+3)

    const int arow0 = tm + (lane & 7) + 8 * ((lane >> 3) & 1);
    const int ac    = lane >> 4;              // 16B col half
    const int brow0 = tn + (lane & 7) + 8 * (lane >> 4);
    const int bc    = (lane >> 3) & 1;
    const unsigned aBase0 = (unsigned)(arow0 * 256),       aX0 = (unsigned)(arow0 & 7);
    const unsigned aBase1 = (unsigned)((arow0 + 16) * 256), aX1 = (unsigned)((arow0 + 16) & 7);
    const unsigned bBase0 = (unsigned)(brow0 * 256),       bX0 = (unsigned)(brow0 & 7);
    const unsigned bBase1 = (unsigned)((brow0 + 16) * 256), bX1 = (unsigned)((brow0 + 16) & 7);

    float acc[2][4][4];
#pragma unroll
    for (int mi = 0; mi < 2; ++mi)
#pragma unroll
        for (int ni = 0; ni < 4; ++ni)
#pragma unroll
            for (int r = 0; r < 4; ++r) acc[mi][ni][r] = 0.0f;

    float4 pre[8];
#pragma unroll
    for (int j = 0; j < 4; ++j) {
        pre[2 * j]     = src[8 * j];
        pre[2 * j + 1] = src[8 * j + 1];
    }

    for (int c = 0; c < NCH; ++c) {
        const int st = c & 1;
        const unsigned sb = stbase + (unsigned)st * 16384u;
        // convert + STS (16B per unit)
#pragma unroll
        for (int j = 0; j < 4; ++j) {
            const float4 f0 = pre[2 * j], f1 = pre[2 * j + 1];
            __nv_bfloat162 p0 = __floats2bfloat162_rn(f0.x, f0.y);
            __nv_bfloat162 p1 = __floats2bfloat162_rn(f0.z, f0.w);
            __nv_bfloat162 p2 = __floats2bfloat162_rn(f1.x, f1.y);
            __nv_bfloat162 p3 = __floats2bfloat162_rn(f1.z, f1.w);
            asm volatile("st.shared.v4.b32 [%0], {%1,%2,%3,%4};"
                :: "r"(sb + sts_off[j]),
                   "r"(*(unsigned*)&p0), "r"(*(unsigned*)&p1),
                   "r"(*(unsigned*)&p2), "r"(*(unsigned*)&p3) : "memory");
        }
        __syncthreads();
        if (c + 1 < NCH) {
            const float4* nsrc = src + (c + 1) * 32;
#pragma unroll
            for (int j = 0; j < 4; ++j) {
                pre[2 * j]     = nsrc[8 * j];
                pre[2 * j + 1] = nsrc[8 * j + 1];
            }
        }
        // MMA over this stage: 4 ksteps for this k-group
#pragma unroll
        for (int u = 0; u < 4; ++u) {
            const int kk = kg * 4 + u;
            const unsigned ca = (unsigned)(2 * kk + ac);
            const unsigned cb = (unsigned)(2 * kk + bc);
            unsigned a0, a1, a2, a3, a4, a5, a6, a7;
            unsigned b0, b1, b2, b3, b4, b5, b6, b7;
            ldsm_x4(sb + aBase0 + ((ca ^ aX0) << 4), a0, a1, a2, a3);
            ldsm_x4(sb + aBase1 + ((ca ^ aX1) << 4), a4, a5, a6, a7);
            ldsm_x4(sb + bBase0 + ((cb ^ bX0) << 4), b0, b1, b2, b3);
            ldsm_x4(sb + bBase1 + ((cb ^ bX1) << 4), b4, b5, b6, b7);
            mma_bf16(acc[0][0], a0, a1, a2, a3, b0, b1);
            mma_bf16(acc[0][1], a0, a1, a2, a3, b2, b3);
            mma_bf16(acc[0][2], a0, a1, a2, a3, b4, b5);
            mma_bf16(acc[0][3], a0, a1, a2, a3, b6, b7);
            mma_bf16(acc[1][0], a4, a5, a6, a7, b0, b1);
            mma_bf16(acc[1][1], a4, a5, a6, a7, b2, b3);
            mma_bf16(acc[1][2], a4, a5, a6, a7, b4, b5);
            mma_bf16(acc[1][3], a4, a5, a6, a7, b6, b7);
        }
    }

    // ---- epilogue: combine the two k-group partials via smem, write g_part
    __syncthreads();
    float* stg = reinterpret_cast<float*>(&tile[0][0]);   // 16 KB staging
    const int crow = lane >> 2, ccol2 = (lane & 3) * 2;
    if (kg == 1) {
#pragma unroll
        for (int mi = 0; mi < 2; ++mi)
#pragma unroll
            for (int ni = 0; ni < 4; ++ni) {
                float* p = stg + tlid * 1024 + (mi * 16 + crow) * 32 + ni * 8 + ccol2;
                p[0] = acc[mi][ni][0]; p[1] = acc[mi][ni][1];
                p[8 * 32] = acc[mi][ni][2]; p[8 * 32 + 1] = acc[mi][ni][3];
            }
    }
    __syncthreads();
    if (kg == 0) {
        float* gp = g_part + (size_t)(b * SPLITS + s) * 4096;
#pragma unroll
        for (int mi = 0; mi < 2; ++mi)
#pragma unroll
            for (int ni = 0; ni < 4; ++ni) {
                const float* p = stg + tlid * 1024 + (mi * 16 + crow) * 32 + ni * 8 + ccol2;
                const int gr = tm + mi * 16 + crow, gc = tn + ni * 8 + ccol2;
                *reinterpret_cast<float2*>(gp + gr * 64 + gc) =
                    make_float2(acc[mi][ni][0] + p[0], acc[mi][ni][1] + p[1]);
                *reinterpret_cast<float2*>(gp + (gr + 8) * 64 + gc) =
                    make_float2(acc[mi][ni][2] + p[8 * 32], acc[mi][ni][3] + p[8 * 32 + 1]);
            }
    }
}

// ---------------------------------------------------------------------------
// Kernel 2: fused tail. grid = 64 CTAs (all resident), 256 threads.
// CTA i: fold 4 split-partials -> g_mat[i]; grid-barrier; D row i + Sn[i];
// grid-barrier; last CTA computes the scalar loss.
// Target dtype detected at runtime (JAX x64-off demotes int64 -> int32).
// ---------------------------------------------------------------------------
__global__ __launch_bounds__(256, 1) void tail_kernel(const void* __restrict__ tgt_raw,
                                                      float* __restrict__ out) {
    __shared__ float gi[4096];
    __shared__ float Drow[64];
    __shared__ float Sns[64];
    __shared__ int   Tg[64];
    __shared__ int   is64s;
    __shared__ int   lastf;
    __shared__ float red[256];
    __shared__ int   redc[256];

    const int tid = threadIdx.x, wid = tid >> 5, lane = tid & 31;
    const int i = blockIdx.x;
    const float inv = 1.0f / ((float)CDIM * (float)WDIM);

    if (tid == 0) {
        const int* t32 = (const int*)tgt_raw;
        int f = 0;
#pragma unroll
        for (int k = 1; k < 64; k += 2) f |= t32[k];
        is64s = (f == 0) ? 1 : 0;
    }

    // fold splits + normalize; publish g_mat[i]
    const float* base = g_part + (size_t)i * SPLITS * 4096;
    for (int t = tid; t < 4096; t += 256) {
        float v = (base[t] + base[4096 + t]) + (base[8192 + t] + base[12288 + t]);
        v *= inv;
        gi[t] = v;
        g_mat[(size_t)i * 4096 + t] = v;
    }
    __threadfence();
    __syncthreads();
    if (tid == 0) {
        atomicAdd(&g_cnt1, 1);
        while (atomicAdd(&g_cnt1, 0) < 64) { __nanosleep(64); }
    }
    __syncthreads();
    __threadfence();

    if (tid < 64)
        Tg[tid] = is64s ? (int)((const long long*)tgt_raw)[tid] : ((const int*)tgt_raw)[tid];

    // distances: warp w handles j = w, w+8, ...
    const float4* gis = reinterpret_cast<const float4*>(gi);
    for (int j = wid; j < BATCH; j += 8) {
        const float4* gj = reinterpret_cast<const float4*>(g_mat + (size_t)j * 4096);
        float sum = 0.0f;
#pragma unroll 4
        for (int cq = lane; cq < 1024; cq += 32) {
            float4 a = gis[cq], bq = gj[cq];
            float e0 = a.x - bq.x, e1 = a.y - bq.y, e2 = a.z - bq.z, e3 = a.w - bq.w;
            sum = fmaf(e0, e0, sum); sum = fmaf(e1, e1, sum);
            sum = fmaf(e2, e2, sum); sum = fmaf(e3, e3, sum);
        }
#pragma unroll
        for (int o = 16; o > 0; o >>= 1) sum += __shfl_xor_sync(0xffffffffu, sum, o);
        if (lane == 0) {
            float dv = sum * (1.0f / 4096.0f);
            Drow[j] = dv;
            d_mat[i * 64 + j] = dv;
        }
    }
    __syncthreads();

    if (wid == 0) {
        const int ti = Tg[i];
        float ssum = 0.0f;
        for (int k = lane; k < 64; k += 32)
            if (Tg[k] != ti) ssum += expf(1.0f - Drow[k]);
#pragma unroll
        for (int o = 16; o > 0; o >>= 1) ssum += __shfl_xor_sync(0xffffffffu, ssum, o);
        if (lane == 0) g_Sn[i] = ssum;
    }
    __threadfence();
    __syncthreads();
    if (tid == 0) lastf = (atomicAdd(&g_cnt2, 1) == 63) ? 1 : 0;
    __syncthreads();
    if (!lastf) return;
    __threadfence();

    // last CTA: final loss (reuse gi as D)
    for (int t = tid; t < 4096; t += 256) gi[t] = d_mat[t];
    if (tid < 64) Sns[tid] = g_Sn[tid];
    __syncthreads();

    float acc = 0.0f;
    int cnt = 0;
    for (int p = tid; p < 4096; p += 256) {
        const int ii = p >> 6, jj = p & 63;
        if (jj > ii && Tg[ii] == Tg[jj]) {
            float Jv = logf(Sns[ii] + Sns[jj]) + gi[p];
            Jv = fmaxf(Jv, 0.0f);
            acc = fmaf(Jv, Jv, acc);
            cnt++;
        }
    }
    red[tid] = acc;
    redc[tid] = cnt;
    __syncthreads();
    for (int o = 128; o > 0; o >>= 1) {
        if (tid < o) { red[tid] += red[tid + o]; redc[tid] += redc[tid + o]; }
        __syncthreads();
    }
    if (tid == 0) out[0] = red[0] / (2.0f * (float)redc[0]);
}

// ---------------------------------------------------------------------------
extern "C" void kernel_launch(void* const* d_in, const int* in_sizes, int n_in,
                              void* d_out, int out_size) {
    const float* inp = (const float*)d_in[0];
    const void*  tgt = (const void*)d_in[1];
    float*       out = (float*)d_out;

    gram_kernel<<<BATCH * SPLITS, 256>>>(inp);
    tail_kernel<<<BATCH, 256>>>(tgt, out);
}

// round 14
// speedup vs baseline: 3.1154x; 1.2588x over previous
#include <cuda_runtime.h>
#include <cuda_bf16.h>
#include <cstdint>

#define BATCH   64
#define CDIM    64
#define WDIM    16384
#define SPLITS  4
#define KSP     (WDIM / SPLITS)      // 4096 fp32 cols per CTA
#define KTF     128                  // fp32 cols per chunk
#define NCH     (KSP / KTF)          // 32 chunks
#define TGRID   256                  // tail grid (64 batches x 4 quarters)

// Scratch (static device arrays; no allocation)
__device__ float g_part[BATCH * SPLITS * 4096];   // 4 MB
__device__ float g_mat [BATCH * 4096];            // 1 MB
__device__ float d_mat [BATCH * BATCH];
__device__ float g_Snp [BATCH * 4];               // per-quarter Sn partials
__device__ int   g_cnt1, g_cnt2;

__device__ __forceinline__ unsigned cvta_s(const void* p) {
    return (unsigned)__cvta_generic_to_shared(p);
}

__device__ __forceinline__ void ldsm_x4(unsigned addr, unsigned &r0, unsigned &r1,
                                        unsigned &r2, unsigned &r3) {
    asm volatile("ldmatrix.sync.aligned.m8n8.x4.shared.b16 {%0,%1,%2,%3}, [%4];\n"
                 : "=r"(r0), "=r"(r1), "=r"(r2), "=r"(r3) : "r"(addr));
}

__device__ __forceinline__ void mma_bf16(float* c, unsigned a0, unsigned a1,
                                         unsigned a2, unsigned a3,
                                         unsigned b0, unsigned b1) {
    asm volatile(
        "mma.sync.aligned.m16n8k16.row.col.f32.bf16.bf16.f32 "
        "{%0,%1,%2,%3}, {%4,%5,%6,%7}, {%8,%9}, {%0,%1,%2,%3};\n"
        : "+f"(c[0]), "+f"(c[1]), "+f"(c[2]), "+f"(c[3])
        : "r"(a0), "r"(a1), "r"(a2), "r"(a3), "r"(b0), "r"(b1));
}

// ---------------------------------------------------------------------------
// Kernel 1: partial Grams. grid = 256 (batch x split), 256 threads, occ 2.
// (unchanged from R11 passing version; measured ~53 us)
// ---------------------------------------------------------------------------
__global__ __launch_bounds__(256, 2) void gram_kernel(const float* __restrict__ inp) {
    __shared__ __align__(1024) __nv_bfloat16 tile[2][64 * 128];   // 2 x 16 KB

    const int tid = threadIdx.x, wid = tid >> 5, lane = tid & 31;
    const int bid = blockIdx.x, b = bid >> 2, s = bid & 3;

    if (bid == 0 && tid == 0) { g_cnt1 = 0; g_cnt2 = 0; }   // grid-barrier reset

    // ---- loader mapping: row = tid>>2 (0..63), q = tid&3; 8 float4/chunk
    const int row = tid >> 2, q = tid & 3, rx = row & 7;
    const float4* src = reinterpret_cast<const float4*>(inp)
                      + (long)(b * CDIM + row) * (WDIM / 4) + s * (KSP / 4) + 2 * q;
    const unsigned stbase = cvta_s(&tile[0][0]);
    unsigned sts_off[4];
#pragma unroll
    for (int j = 0; j < 4; ++j)
        sts_off[j] = (unsigned)(row * 256 + (((4 * j + q) ^ rx) << 4));

    // ---- MMA mapping
    const int tlid = wid & 3;
    const int tm = (tlid & 1) * 32, tn = (tlid >> 1) * 32;
    const int kg = wid >> 2;

    const int arow0 = tm + (lane & 7) + 8 * ((lane >> 3) & 1);
    const int ac    = lane >> 4;
    const int brow0 = tn + (lane & 7) + 8 * (lane >> 4);
    const int bc    = (lane >> 3) & 1;
    const unsigned aBase0 = (unsigned)(arow0 * 256),        aX0 = (unsigned)(arow0 & 7);
    const unsigned aBase1 = (unsigned)((arow0 + 16) * 256), aX1 = (unsigned)((arow0 + 16) & 7);
    const unsigned bBase0 = (unsigned)(brow0 * 256),        bX0 = (unsigned)(brow0 & 7);
    const unsigned bBase1 = (unsigned)((brow0 + 16) * 256), bX1 = (unsigned)((brow0 + 16) & 7);

    float acc[2][4][4];
#pragma unroll
    for (int mi = 0; mi < 2; ++mi)
#pragma unroll
        for (int ni = 0; ni < 4; ++ni)
#pragma unroll
            for (int r = 0; r < 4; ++r) acc[mi][ni][r] = 0.0f;

    float4 pre[8];
#pragma unroll
    for (int j = 0; j < 4; ++j) {
        pre[2 * j]     = src[8 * j];
        pre[2 * j + 1] = src[8 * j + 1];
    }

    for (int c = 0; c < NCH; ++c) {
        const int st = c & 1;
        const unsigned sb = stbase + (unsigned)st * 16384u;
#pragma unroll
        for (int j = 0; j < 4; ++j) {
            const float4 f0 = pre[2 * j], f1 = pre[2 * j + 1];
            __nv_bfloat162 p0 = __floats2bfloat162_rn(f0.x, f0.y);
            __nv_bfloat162 p1 = __floats2bfloat162_rn(f0.z, f0.w);
            __nv_bfloat162 p2 = __floats2bfloat162_rn(f1.x, f1.y);
            __nv_bfloat162 p3 = __floats2bfloat162_rn(f1.z, f1.w);
            asm volatile("st.shared.v4.b32 [%0], {%1,%2,%3,%4};"
                :: "r"(sb + sts_off[j]),
                   "r"(*(unsigned*)&p0), "r"(*(unsigned*)&p1),
                   "r"(*(unsigned*)&p2), "r"(*(unsigned*)&p3) : "memory");
        }
        __syncthreads();
        if (c + 1 < NCH) {
            const float4* nsrc = src + (c + 1) * 32;
#pragma unroll
            for (int j = 0; j < 4; ++j) {
                pre[2 * j]     = nsrc[8 * j];
                pre[2 * j + 1] = nsrc[8 * j + 1];
            }
        }
#pragma unroll
        for (int u = 0; u < 4; ++u) {
            const int kk = kg * 4 + u;
            const unsigned ca = (unsigned)(2 * kk + ac);
            const unsigned cb = (unsigned)(2 * kk + bc);
            unsigned a0, a1, a2, a3, a4, a5, a6, a7;
            unsigned b0, b1, b2, b3, b4, b5, b6, b7;
            ldsm_x4(sb + aBase0 + ((ca ^ aX0) << 4), a0, a1, a2, a3);
            ldsm_x4(sb + aBase1 + ((ca ^ aX1) << 4), a4, a5, a6, a7);
            ldsm_x4(sb + bBase0 + ((cb ^ bX0) << 4), b0, b1, b2, b3);
            ldsm_x4(sb + bBase1 + ((cb ^ bX1) << 4), b4, b5, b6, b7);
            mma_bf16(acc[0][0], a0, a1, a2, a3, b0, b1);
            mma_bf16(acc[0][1], a0, a1, a2, a3, b2, b3);
            mma_bf16(acc[0][2], a0, a1, a2, a3, b4, b5);
            mma_bf16(acc[0][3], a0, a1, a2, a3, b6, b7);
            mma_bf16(acc[1][0], a4, a5, a6, a7, b0, b1);
            mma_bf16(acc[1][1], a4, a5, a6, a7, b2, b3);
            mma_bf16(acc[1][2], a4, a5, a6, a7, b4, b5);
            mma_bf16(acc[1][3], a4, a5, a6, a7, b6, b7);
        }
    }

    // ---- epilogue: combine the two k-group partials via smem, write g_part
    __syncthreads();
    float* stg = reinterpret_cast<float*>(&tile[0][0]);
    const int crow = lane >> 2, ccol2 = (lane & 3) * 2;
    if (kg == 1) {
#pragma unroll
        for (int mi = 0; mi < 2; ++mi)
#pragma unroll
            for (int ni = 0; ni < 4; ++ni) {
                float* p = stg + tlid * 1024 + (mi * 16 + crow) * 32 + ni * 8 + ccol2;
                p[0] = acc[mi][ni][0]; p[1] = acc[mi][ni][1];
                p[8 * 32] = acc[mi][ni][2]; p[8 * 32 + 1] = acc[mi][ni][3];
            }
    }
    __syncthreads();
    if (kg == 0) {
        float* gp = g_part + (size_t)(b * SPLITS + s) * 4096;
#pragma unroll
        for (int mi = 0; mi < 2; ++mi)
#pragma unroll
            for (int ni = 0; ni < 4; ++ni) {
                const float* p = stg + tlid * 1024 + (mi * 16 + crow) * 32 + ni * 8 + ccol2;
                const int gr = tm + mi * 16 + crow, gc = tn + ni * 8 + ccol2;
                *reinterpret_cast<float2*>(gp + gr * 64 + gc) =
                    make_float2(acc[mi][ni][0] + p[0], acc[mi][ni][1] + p[1]);
                *reinterpret_cast<float2*>(gp + (gr + 8) * 64 + gc) =
                    make_float2(acc[mi][ni][2] + p[8 * 32], acc[mi][ni][3] + p[8 * 32 + 1]);
            }
    }
}

// ---------------------------------------------------------------------------
// Kernel 2: fused tail. grid = 256 CTAs (all resident at occ 2), 256 threads.
// CTA (i = bid>>2, qd = bid&3):
//   P1: fold quarter qd of batch i -> g_mat
//   grid-barrier
//   P2: load full g_mat[i] to smem; compute D[i][j] for 16 j's (8 warps x 2 j,
//       interleaved for MLP); per-quarter Sn partial -> g_Snp (deterministic)
//   grid-barrier (ticket); last CTA computes the scalar loss.
// Target dtype detected at runtime (JAX x64-off demotes int64 -> int32).
// ---------------------------------------------------------------------------
__global__ __launch_bounds__(256, 2) void tail_kernel(const void* __restrict__ tgt_raw,
                                                      float* __restrict__ out) {
    __shared__ __align__(16) float gi[4096];
    __shared__ float Sns[64];
    __shared__ int   Tg[64];
    __shared__ int   is64s;
    __shared__ int   lastf;
    __shared__ float wsn[8];
    __shared__ float red[256];
    __shared__ int   redc[256];

    const int tid = threadIdx.x, wid = tid >> 5, lane = tid & 31;
    const int i = blockIdx.x >> 2, qd = blockIdx.x & 3;
    const float inv = 1.0f / ((float)CDIM * (float)WDIM);

    if (tid == 0) {
        const int* t32 = (const int*)tgt_raw;
        int f = 0;
#pragma unroll
        for (int k = 1; k < 64; k += 2) f |= t32[k];
        is64s = (f == 0) ? 1 : 0;
    }
    __syncthreads();
    if (tid < 64)
        Tg[tid] = is64s ? (int)((const long long*)tgt_raw)[tid] : ((const int*)tgt_raw)[tid];

    // ---- P1: fold quarter qd of batch i (256 float4 / 256 threads)
    {
        const float4* b0 = reinterpret_cast<const float4*>(
            g_part + (size_t)i * SPLITS * 4096 + qd * 1024) + tid;
        const float4* b1 = b0 + 1024;   // +4096 floats
        const float4* b2 = b1 + 1024;
        const float4* b3 = b2 + 1024;
        float4 v0 = *b0, v1 = *b1, v2 = *b2, v3 = *b3;
        float4 r;
        r.x = ((v0.x + v1.x) + (v2.x + v3.x)) * inv;
        r.y = ((v0.y + v1.y) + (v2.y + v3.y)) * inv;
        r.z = ((v0.z + v1.z) + (v2.z + v3.z)) * inv;
        r.w = ((v0.w + v1.w) + (v2.w + v3.w)) * inv;
        reinterpret_cast<float4*>(g_mat + (size_t)i * 4096 + qd * 1024)[tid] = r;
    }
    __threadfence();
    __syncthreads();
    if (tid == 0) {
        atomicAdd(&g_cnt1, 1);
        while (atomicAdd(&g_cnt1, 0) < TGRID) { __nanosleep(64); }
    }
    __syncthreads();
    __threadfence();

    // ---- P2: load gi, compute 16 distances (2 j's per warp, interleaved)
    {
        const float4* gsrc = reinterpret_cast<const float4*>(g_mat + (size_t)i * 4096);
        float4* gi4 = reinterpret_cast<float4*>(gi);
        for (int t = tid; t < 1024; t += 256) gi4[t] = gsrc[t];
    }
    __syncthreads();

    const int j0 = qd * 16 + wid * 2;
    const int j1 = j0 + 1;
    {
        const float4* gj0 = reinterpret_cast<const float4*>(g_mat + (size_t)j0 * 4096);
        const float4* gj1 = reinterpret_cast<const float4*>(g_mat + (size_t)j1 * 4096);
        const float4* gi4 = reinterpret_cast<const float4*>(gi);
        float s0 = 0.0f, s1 = 0.0f;
#pragma unroll 4
        for (int cq = lane; cq < 1024; cq += 32) {
            const float4 a  = gi4[cq];
            const float4 p  = gj0[cq];
            const float4 r  = gj1[cq];
            float e;
            e = a.x - p.x; s0 = fmaf(e, e, s0);
            e = a.y - p.y; s0 = fmaf(e, e, s0);
            e = a.z - p.z; s0 = fmaf(e, e, s0);
            e = a.w - p.w; s0 = fmaf(e, e, s0);
            e = a.x - r.x; s1 = fmaf(e, e, s1);
            e = a.y - r.y; s1 = fmaf(e, e, s1);
            e = a.z - r.z; s1 = fmaf(e, e, s1);
            e = a.w - r.w; s1 = fmaf(e, e, s1);
        }
#pragma unroll
        for (int o = 16; o > 0; o >>= 1) {
            s0 += __shfl_xor_sync(0xffffffffu, s0, o);
            s1 += __shfl_xor_sync(0xffffffffu, s1, o);
        }
        if (lane == 0) {
            const float d0 = s0 * (1.0f / 4096.0f);
            const float d1 = s1 * (1.0f / 4096.0f);
            d_mat[i * 64 + j0] = d0;
            d_mat[i * 64 + j1] = d1;
            const int ti = Tg[i];
            float sn = 0.0f;
            if (Tg[j0] != ti) sn += expf(1.0f - d0);
            if (Tg[j1] != ti) sn += expf(1.0f - d1);
            wsn[wid] = sn;
        }
    }
    __syncthreads();
    if (tid == 0) {
        float sn = 0.0f;
#pragma unroll
        for (int w = 0; w < 8; ++w) sn += wsn[w];
        g_Snp[i * 4 + qd] = sn;
    }
    __threadfence();
    __syncthreads();
    if (tid == 0) lastf = (atomicAdd(&g_cnt2, 1) == TGRID - 1) ? 1 : 0;
    __syncthreads();
    if (!lastf) return;
    __threadfence();

    // ---- P3: final loss in the last-arriving CTA (reuse gi as D)
    for (int t = tid; t < 4096; t += 256) gi[t] = d_mat[t];
    if (tid < 64) {
        const float* sp = g_Snp + tid * 4;
        Sns[tid] = (sp[0] + sp[1]) + (sp[2] + sp[3]);
    }
    __syncthreads();

    float acc = 0.0f;
    int cnt = 0;
    for (int p = tid; p < 4096; p += 256) {
        const int ii = p >> 6, jj = p & 63;
        if (jj > ii && Tg[ii] == Tg[jj]) {
            float Jv = logf(Sns[ii] + Sns[jj]) + gi[p];
            Jv = fmaxf(Jv, 0.0f);
            acc = fmaf(Jv, Jv, acc);
            cnt++;
        }
    }
    red[tid] = acc;
    redc[tid] = cnt;
    __syncthreads();
    for (int o = 128; o > 0; o >>= 1) {
        if (tid < o) { red[tid] += red[tid + o]; redc[tid] += redc[tid + o]; }
        __syncthreads();
    }
    if (tid == 0) out[0] = red[0] / (2.0f * (float)redc[0]);
}

// ---------------------------------------------------------------------------
extern "C" void kernel_launch(void* const* d_in, const int* in_sizes, int n_in,
                              void* d_out, int out_size) {
    const float* inp = (const float*)d_in[0];
    const void*  tgt = (const void*)d_in[1];
    float*       out = (float*)d_out;

    gram_kernel<<<BATCH * SPLITS, 256>>>(inp);
    tail_kernel<<<TGRID, 256>>>(tgt, out);
}